// round 11
// baseline (speedup 1.0000x reference)
#include <cuda_runtime.h>
#include <float.h>
#include <math.h>
#include <cstdint>

// x = [B=16, C=2048, H=48, W=64] fp32. 21 regions; 6 row ranges from 6 row
// segments (breakpoints 0,12,16,24,32,36,48).
#define B_  16
#define C_  2048
#define H_  48
#define W_  64
#define NPLANE (B_ * C_)
#define R_  21
#define EPS_ 1e-6f

#define CHUNKS_   8                      // partial-sum chunks per batch
#define CH_PER_CHUNK (C_ / CHUNKS_)      // 256 channels
#define CHUNK_FLOATS (CH_PER_CHUNK * R_) // 5376 floats = 21504 B (16B-aligned)

// vecs layout: [b][c][r]  (element (b,c,r) at (b*C + c)*R + r)
__device__ float g_vecs[B_ * C_ * R_];
__device__ float g_part[B_ * R_ * CHUNKS_];   // per-(b,r) partial sumsq

// RR0=[0,48) RR1=[0,32) RR2=[16,48) RR3=[0,24) RR4=[12,36) RR5=[24,48)
__constant__ int REG_RR[R_] = {
    0,
    0, 0,
    1, 1, 1,
    2, 2, 2,
    3, 3, 3, 3,
    4, 4, 4, 4,
    5, 5, 5, 5
};
__constant__ int REG_C0[R_] = {
    0,
    0, 16,
    0, 16, 32,
    0, 16, 32,
    0, 13, 26, 40,
    0, 13, 26, 40,
    0, 13, 26, 40
};
__constant__ int REG_C1[R_] = {
    64,
    48, 64,
    32, 48, 64,
    32, 48, 64,
    24, 37, 50, 64,
    24, 37, 50, 64,
    24, 37, 50, 64
};

// ---------------------------------------------------------------------------
// Kernel 1 (frozen roofline config): one block per (b,c) plane, 64 threads =
// one per column. Scalar coalesced LDG.32 column-walk, 6 segment maxes in
// registers, 6 row-range maxes in smem, 21 region reductions. Stores to the
// [b][c][r] layout (21 contiguous floats per plane).
// ---------------------------------------------------------------------------
__global__ __launch_bounds__(64) void rpool_max_kernel(
    const float* __restrict__ x, float* __restrict__ vecs)
{
    const int plane = blockIdx.x;             // b * C + c
    const float* __restrict__ p = x + (size_t)plane * (H_ * W_);
    const int col = threadIdx.x;              // 0..63

    float s0 = -FLT_MAX, s1 = -FLT_MAX, s2 = -FLT_MAX;
    float s3 = -FLT_MAX, s4 = -FLT_MAX, s5 = -FLT_MAX;

    #pragma unroll
    for (int r = 0; r < 12; r++)  s0 = fmaxf(s0, p[r * W_ + col]);
    #pragma unroll
    for (int r = 12; r < 16; r++) s1 = fmaxf(s1, p[r * W_ + col]);
    #pragma unroll
    for (int r = 16; r < 24; r++) s2 = fmaxf(s2, p[r * W_ + col]);
    #pragma unroll
    for (int r = 24; r < 32; r++) s3 = fmaxf(s3, p[r * W_ + col]);
    #pragma unroll
    for (int r = 32; r < 36; r++) s4 = fmaxf(s4, p[r * W_ + col]);
    #pragma unroll
    for (int r = 36; r < 48; r++) s5 = fmaxf(s5, p[r * W_ + col]);

    __shared__ float rr[6][W_];
    const float m012 = fmaxf(fmaxf(s0, s1), s2);
    const float m345 = fmaxf(fmaxf(s3, s4), s5);
    rr[0][col] = fmaxf(m012, m345);                     // rows [0,48)
    rr[1][col] = fmaxf(m012, s3);                       // rows [0,32)
    rr[2][col] = fmaxf(fmaxf(s2, s3), fmaxf(s4, s5));   // rows [16,48)
    rr[3][col] = m012;                                  // rows [0,24)
    rr[4][col] = fmaxf(fmaxf(s1, s2), fmaxf(s3, s4));   // rows [12,36)
    rr[5][col] = m345;                                  // rows [24,48)
    __syncthreads();

    const int warp = threadIdx.x >> 5;
    const int lane = threadIdx.x & 31;

    for (int reg = warp; reg < R_; reg += 2) {
        const int ri = REG_RR[reg];
        const int c0 = REG_C0[reg];
        const int c1 = REG_C1[reg];
        float m = -FLT_MAX;
        for (int cc = c0 + lane; cc < c1; cc += 32)
            m = fmaxf(m, rr[ri][cc]);
        #pragma unroll
        for (int o = 16; o > 0; o >>= 1)
            m = fmaxf(m, __shfl_xor_sync(0xffffffffu, m, o));
        if (lane == 0)
            vecs[(size_t)plane * R_ + reg] = m;    // [b][c][r] layout
    }
}

// ---------------------------------------------------------------------------
// Kernel 2: partial sums of squares. grid = 128 (16 batches x 8 chunks),
// 256 threads. Block reads its contiguous 21KB chunk (256 channels x 21
// regions) into smem, then 8 warps compute the 21 per-region partial
// sums of squares. Side effect: pulls the whole slab into L2 for kernel 3.
// ---------------------------------------------------------------------------
__global__ __launch_bounds__(256) void rpool_part_kernel(
    const float* __restrict__ vecs, float* __restrict__ part)
{
    const int b = blockIdx.x >> 3;             // /8
    const int chunk = blockIdx.x & 7;
    const int tid = threadIdx.x;
    const int warp = tid >> 5, lane = tid & 31;

    __shared__ float sl[CHUNK_FLOATS];         // [256 ch][21 r]

    const float4* __restrict__ src4 = reinterpret_cast<const float4*>(
        vecs + ((size_t)b * C_ + chunk * CH_PER_CHUNK) * R_);
    float4* __restrict__ sl4 = reinterpret_cast<float4*>(sl);
    #pragma unroll
    for (int i = tid; i < CHUNK_FLOATS / 4; i += 256)   // 1344 float4
        sl4[i] = src4[i];
    __syncthreads();

    // warp w handles regions w, w+8, w+16 (if < 21)
    #pragma unroll
    for (int r = warp; r < R_; r += 8) {
        float acc = 0.f;
        #pragma unroll
        for (int k = 0; k < CH_PER_CHUNK / 32; k++) {   // 8 channels/lane
            const float v = sl[(lane + k * 32) * R_ + r];
            acc += v * v;
        }
        #pragma unroll
        for (int o = 16; o > 0; o >>= 1)
            acc += __shfl_xor_sync(0xffffffffu, acc, o);
        if (lane == 0)
            part[((size_t)b * R_ + r) * CHUNKS_ + chunk] = acc;
    }
}

// ---------------------------------------------------------------------------
// Kernel 3: finalize. grid = 16 x 1024 threads. Builds inv norms from the
// 8 partials per region, then aggregates 2 channels per thread (21
// contiguous L2-hot floats each), block-reduces the global norm, stores.
// ---------------------------------------------------------------------------
__global__ __launch_bounds__(1024) void rpool_final_kernel(
    const float* __restrict__ vecs, const float* __restrict__ part,
    float* __restrict__ out)
{
    const int b = blockIdx.x;
    const int tid = threadIdx.x;
    const int warp = tid >> 5, lane = tid & 31;

    __shared__ float inv[R_];
    __shared__ float ws[32];
    __shared__ float s_invn;

    // inv norms: warp w (w < 21) sums its 8 partials
    if (warp < R_) {
        float v = (lane < CHUNKS_)
                ? part[((size_t)b * R_ + warp) * CHUNKS_ + lane] : 0.f;
        #pragma unroll
        for (int o = 4; o > 0; o >>= 1)
            v += __shfl_xor_sync(0xffffffffu, v, o);
        if (lane == 0)
            inv[warp] = 1.0f / (sqrtf(v) + EPS_);
    }
    __syncthreads();

    // aggregate: 2 channels per thread, 21 contiguous L2-hot floats each
    const float* __restrict__ vb = vecs + (size_t)b * C_ * R_;
    float sA = 0.f, sB = 0.f;
    {
        const float* rowA = vb + (size_t)tid * R_;
        const float* rowB = vb + (size_t)(tid + 1024) * R_;
        #pragma unroll
        for (int r = 0; r < R_; r++) {
            sA += rowA[r] * inv[r];
            sB += rowB[r] * inv[r];
        }
    }
    float local = sA * sA + sB * sB;

    #pragma unroll
    for (int o = 16; o > 0; o >>= 1)
        local += __shfl_xor_sync(0xffffffffu, local, o);
    if (lane == 0) ws[warp] = local;
    __syncthreads();
    if (warp == 0) {
        float t = ws[lane];
        #pragma unroll
        for (int o = 16; o > 0; o >>= 1)
            t += __shfl_xor_sync(0xffffffffu, t, o);
        if (lane == 0) s_invn = 1.0f / (sqrtf(t) + EPS_);
    }
    __syncthreads();

    const float invn = s_invn;
    out[(size_t)b * C_ + tid]        = sA * invn;
    out[(size_t)b * C_ + tid + 1024] = sB * invn;
}

extern "C" void kernel_launch(void* const* d_in, const int* in_sizes, int n_in,
                              void* d_out, int out_size)
{
    const float* x = (const float*)d_in[0];
    float* out = (float*)d_out;

    float* vecs;
    float* part;
    cudaGetSymbolAddress((void**)&vecs, g_vecs);
    cudaGetSymbolAddress((void**)&part, g_part);

    rpool_max_kernel<<<NPLANE, 64>>>(x, vecs);
    rpool_part_kernel<<<B_ * CHUNKS_, 256>>>(vecs, part);
    rpool_final_kernel<<<B_, 1024>>>(vecs, part, out);
}

// round 12
// speedup vs baseline: 1.0727x; 1.0727x over previous
#include <cuda_runtime.h>
#include <float.h>
#include <math.h>

// x = [B=16, C=2048, H=48, W=64] fp32. 21 regions; 6 row ranges from 6 row
// segments (breakpoints 0,12,16,24,32,36,48).
#define B_  16
#define C_  2048
#define H_  48
#define W_  64
#define NPLANE (B_ * C_)
#define R_  21
#define EPS_ 1e-6f

__device__ float g_vecs[B_ * R_ * C_];    // [b][r][c]

// RR0=[0,48) RR1=[0,32) RR2=[16,48) RR3=[0,24) RR4=[12,36) RR5=[24,48)
__constant__ int REG_RR[R_] = {
    0,
    0, 0,
    1, 1, 1,
    2, 2, 2,
    3, 3, 3, 3,
    4, 4, 4, 4,
    5, 5, 5, 5
};
__constant__ int REG_C0[R_] = {
    0,
    0, 16,
    0, 16, 32,
    0, 16, 32,
    0, 13, 26, 40,
    0, 13, 26, 40,
    0, 13, 26, 40
};
__constant__ int REG_C1[R_] = {
    64,
    48, 64,
    32, 48, 64,
    32, 48, 64,
    24, 37, 50, 64,
    24, 37, 50, 64,
    24, 37, 50, 64
};

// ---------------------------------------------------------------------------
// Kernel 1 (R4/R8 structure, measured 70.7us): one block per (b,c) plane,
// 64 threads = one per column. Scalar coalesced column-walk with STREAMING
// (evict-first) loads -- the 402MB input has zero reuse, so keep it out of
// the cache hierarchy's retention path. 6 segment maxes in registers, 6
// row-range maxes in smem, 21 region column reductions via shuffles.
// ---------------------------------------------------------------------------
__global__ __launch_bounds__(64) void rpool_max_kernel(
    const float* __restrict__ x, float* __restrict__ vecs)
{
    const int plane = blockIdx.x;             // b * C + c
    const float* __restrict__ p = x + (size_t)plane * (H_ * W_);
    const int col = threadIdx.x;              // 0..63

    float s0 = -FLT_MAX, s1 = -FLT_MAX, s2 = -FLT_MAX;
    float s3 = -FLT_MAX, s4 = -FLT_MAX, s5 = -FLT_MAX;

    #pragma unroll
    for (int r = 0; r < 12; r++)  s0 = fmaxf(s0, __ldcs(p + r * W_ + col));
    #pragma unroll
    for (int r = 12; r < 16; r++) s1 = fmaxf(s1, __ldcs(p + r * W_ + col));
    #pragma unroll
    for (int r = 16; r < 24; r++) s2 = fmaxf(s2, __ldcs(p + r * W_ + col));
    #pragma unroll
    for (int r = 24; r < 32; r++) s3 = fmaxf(s3, __ldcs(p + r * W_ + col));
    #pragma unroll
    for (int r = 32; r < 36; r++) s4 = fmaxf(s4, __ldcs(p + r * W_ + col));
    #pragma unroll
    for (int r = 36; r < 48; r++) s5 = fmaxf(s5, __ldcs(p + r * W_ + col));

    __shared__ float rr[6][W_];
    const float m012 = fmaxf(fmaxf(s0, s1), s2);
    const float m345 = fmaxf(fmaxf(s3, s4), s5);
    rr[0][col] = fmaxf(m012, m345);                     // rows [0,48)
    rr[1][col] = fmaxf(m012, s3);                       // rows [0,32)
    rr[2][col] = fmaxf(fmaxf(s2, s3), fmaxf(s4, s5));   // rows [16,48)
    rr[3][col] = m012;                                  // rows [0,24)
    rr[4][col] = fmaxf(fmaxf(s1, s2), fmaxf(s3, s4));   // rows [12,36)
    rr[5][col] = m345;                                  // rows [24,48)
    __syncthreads();

    const int warp = threadIdx.x >> 5;
    const int lane = threadIdx.x & 31;
    const int b = plane >> 11;          // / C_
    const int c = plane & (C_ - 1);     // % C_

    for (int reg = warp; reg < R_; reg += 2) {
        const int ri = REG_RR[reg];
        const int c0 = REG_C0[reg];
        const int c1 = REG_C1[reg];
        float m = -FLT_MAX;
        for (int cc = c0 + lane; cc < c1; cc += 32)
            m = fmaxf(m, rr[ri][cc]);
        #pragma unroll
        for (int o = 16; o > 0; o >>= 1)
            m = fmaxf(m, __shfl_xor_sync(0xffffffffu, m, o));
        if (lane == 0)
            vecs[((size_t)(b * R_ + reg)) * C_ + c] = m;
    }
}

// ---------------------------------------------------------------------------
// Kernel 2 (R8-exact fused backend, best measured): grid = 16 blocks (one
// per batch) x 672 threads (21 warps).
// Pass 1: warp r reduces region r's sum of squares -> inv[r] in smem.
// Pass 2: threads 0-511 weighted region sum (21 float4 loads each),
//         block-reduce the global norm across 21 warps, store.
// ---------------------------------------------------------------------------
__global__ __launch_bounds__(672) void rpool_normagg_kernel(
    const float* __restrict__ vecs, float* __restrict__ out)
{
    const int b = blockIdx.x;
    const int tid = threadIdx.x;
    const int warp = tid >> 5;                 // 0..20
    const int lane = tid & 31;
    const float4* __restrict__ vb4 =
        reinterpret_cast<const float4*>(vecs + (size_t)b * R_ * C_);

    __shared__ float inv[R_];

    // ---- pass 1: warp-per-region L2 norm ----
    {
        const int r = warp;                    // every warp owns one region
        const float4* __restrict__ vr = vb4 + r * 512;
        float acc = 0.f;
        #pragma unroll
        for (int k = 0; k < 16; k++) {
            const float4 v = vr[lane + k * 32];
            acc += v.x * v.x + v.y * v.y + v.z * v.z + v.w * v.w;
        }
        #pragma unroll
        for (int o = 16; o > 0; o >>= 1)
            acc += __shfl_xor_sync(0xffffffffu, acc, o);
        if (lane == 0)
            inv[r] = 1.0f / (sqrtf(acc) + EPS_);
    }
    __syncthreads();

    // ---- pass 2: aggregate + global L2 normalize ----
    float4 s = make_float4(0.f, 0.f, 0.f, 0.f);
    float local = 0.f;
    if (tid < 512) {
        #pragma unroll
        for (int r = 0; r < R_; r++) {
            const float4 v = vb4[r * 512 + tid];
            const float k = inv[r];
            s.x += v.x * k; s.y += v.y * k;
            s.z += v.z * k; s.w += v.w * k;
        }
        local = s.x * s.x + s.y * s.y + s.z * s.z + s.w * s.w;
    }

    #pragma unroll
    for (int o = 16; o > 0; o >>= 1)
        local += __shfl_xor_sync(0xffffffffu, local, o);
    __shared__ float ws[R_];
    if (lane == 0) ws[warp] = local;
    __syncthreads();
    __shared__ float s_invn;
    if (warp == 0) {
        float t = (lane < R_) ? ws[lane] : 0.f;
        #pragma unroll
        for (int o = 16; o > 0; o >>= 1)
            t += __shfl_xor_sync(0xffffffffu, t, o);
        if (lane == 0) s_invn = 1.0f / (sqrtf(t) + EPS_);
    }
    __syncthreads();

    if (tid < 512) {
        const float invn = s_invn;
        s.x *= invn; s.y *= invn; s.z *= invn; s.w *= invn;
        reinterpret_cast<float4*>(out)[(size_t)b * 512 + tid] = s;
    }
}

extern "C" void kernel_launch(void* const* d_in, const int* in_sizes, int n_in,
                              void* d_out, int out_size)
{
    const float* x = (const float*)d_in[0];
    float* out = (float*)d_out;

    float* vecs;
    cudaGetSymbolAddress((void**)&vecs, g_vecs);

    rpool_max_kernel<<<NPLANE, 64>>>(x, vecs);
    rpool_normagg_kernel<<<B_, 672>>>(vecs, out);
}

// round 13
// speedup vs baseline: 1.0811x; 1.0078x over previous
#include <cuda_runtime.h>
#include <float.h>
#include <math.h>

// x = [B=16, C=2048, H=48, W=64] fp32. 21 regions; 6 row ranges from 6 row
// segments (breakpoints 0,12,16,24,32,36,48).
#define B_  16
#define C_  2048
#define H_  48
#define W_  64
#define NPLANE (B_ * C_)
#define R_  21
#define EPS_ 1e-6f

__device__ float g_vecs[B_ * R_ * C_];    // [b][r][c]

// RR0=[0,48) RR1=[0,32) RR2=[16,48) RR3=[0,24) RR4=[12,36) RR5=[24,48)
__constant__ int REG_RR[R_] = {
    0,
    0, 0,
    1, 1, 1,
    2, 2, 2,
    3, 3, 3, 3,
    4, 4, 4, 4,
    5, 5, 5, 5
};
__constant__ int REG_C0[R_] = {
    0,
    0, 16,
    0, 16, 32,
    0, 16, 32,
    0, 13, 26, 40,
    0, 13, 26, 40,
    0, 13, 26, 40
};
__constant__ int REG_C1[R_] = {
    64,
    48, 64,
    32, 48, 64,
    32, 48, 64,
    24, 37, 50, 64,
    24, 37, 50, 64,
    24, 37, 50, 64
};

// ---------------------------------------------------------------------------
// Kernel 1 (R12 config, ~69.4us): one block per (b,c) plane, 64 threads =
// one per column. Streaming (__ldcs) coalesced column-walk, 6 segment maxes
// in registers, 6 row-range maxes in smem, 21 region reductions.
// NEW: griddepcontrol.launch_dependents after the vecs stores -> the PDL
// backend grid gets scheduled while the pool tail drains.
// ---------------------------------------------------------------------------
__global__ __launch_bounds__(64) void rpool_max_kernel(
    const float* __restrict__ x, float* __restrict__ vecs)
{
    const int plane = blockIdx.x;             // b * C + c
    const float* __restrict__ p = x + (size_t)plane * (H_ * W_);
    const int col = threadIdx.x;              // 0..63

    float s0 = -FLT_MAX, s1 = -FLT_MAX, s2 = -FLT_MAX;
    float s3 = -FLT_MAX, s4 = -FLT_MAX, s5 = -FLT_MAX;

    #pragma unroll
    for (int r = 0; r < 12; r++)  s0 = fmaxf(s0, __ldcs(p + r * W_ + col));
    #pragma unroll
    for (int r = 12; r < 16; r++) s1 = fmaxf(s1, __ldcs(p + r * W_ + col));
    #pragma unroll
    for (int r = 16; r < 24; r++) s2 = fmaxf(s2, __ldcs(p + r * W_ + col));
    #pragma unroll
    for (int r = 24; r < 32; r++) s3 = fmaxf(s3, __ldcs(p + r * W_ + col));
    #pragma unroll
    for (int r = 32; r < 36; r++) s4 = fmaxf(s4, __ldcs(p + r * W_ + col));
    #pragma unroll
    for (int r = 36; r < 48; r++) s5 = fmaxf(s5, __ldcs(p + r * W_ + col));

    __shared__ float rr[6][W_];
    const float m012 = fmaxf(fmaxf(s0, s1), s2);
    const float m345 = fmaxf(fmaxf(s3, s4), s5);
    rr[0][col] = fmaxf(m012, m345);                     // rows [0,48)
    rr[1][col] = fmaxf(m012, s3);                       // rows [0,32)
    rr[2][col] = fmaxf(fmaxf(s2, s3), fmaxf(s4, s5));   // rows [16,48)
    rr[3][col] = m012;                                  // rows [0,24)
    rr[4][col] = fmaxf(fmaxf(s1, s2), fmaxf(s3, s4));   // rows [12,36)
    rr[5][col] = m345;                                  // rows [24,48)
    __syncthreads();

    const int warp = threadIdx.x >> 5;
    const int lane = threadIdx.x & 31;
    const int b = plane >> 11;          // / C_
    const int c = plane & (C_ - 1);     // % C_

    for (int reg = warp; reg < R_; reg += 2) {
        const int ri = REG_RR[reg];
        const int c0 = REG_C0[reg];
        const int c1 = REG_C1[reg];
        float m = -FLT_MAX;
        for (int cc = c0 + lane; cc < c1; cc += 32)
            m = fmaxf(m, rr[ri][cc]);
        #pragma unroll
        for (int o = 16; o > 0; o >>= 1)
            m = fmaxf(m, __shfl_xor_sync(0xffffffffu, m, o));
        if (lane == 0)
            vecs[((size_t)(b * R_ + reg)) * C_ + c] = m;
    }

    // All this CTA's vecs stores are above this point: safe to signal.
    asm volatile("griddepcontrol.launch_dependents;" ::: "memory");
}

// ---------------------------------------------------------------------------
// Kernel 2 (R8/R12 fused backend + PDL): grid = 16 blocks x 672 threads
// (21 warps). Launched with programmatic stream serialization: the prologue
// runs while the pool drains; griddepcontrol.wait gates the first vecs load.
// Pass 1: warp r reduces region r's sum of squares -> inv[r] in smem.
// Pass 2: threads 0-511 weighted region sum, block-reduce global norm, store.
// ---------------------------------------------------------------------------
__global__ __launch_bounds__(672) void rpool_normagg_kernel(
    const float* __restrict__ vecs, float* __restrict__ out)
{
    const int b = blockIdx.x;
    const int tid = threadIdx.x;
    const int warp = tid >> 5;                 // 0..20
    const int lane = tid & 31;
    const float4* __restrict__ vb4 =
        reinterpret_cast<const float4*>(vecs + (size_t)b * R_ * C_);

    __shared__ float inv[R_];

    // Wait for all pool CTAs' launch_dependents (memory: their vecs stores
    // are visible after this returns).
    asm volatile("griddepcontrol.wait;" ::: "memory");

    // ---- pass 1: warp-per-region L2 norm ----
    {
        const int r = warp;                    // every warp owns one region
        const float4* __restrict__ vr = vb4 + r * 512;
        float acc = 0.f;
        #pragma unroll
        for (int k = 0; k < 16; k++) {
            const float4 v = vr[lane + k * 32];
            acc += v.x * v.x + v.y * v.y + v.z * v.z + v.w * v.w;
        }
        #pragma unroll
        for (int o = 16; o > 0; o >>= 1)
            acc += __shfl_xor_sync(0xffffffffu, acc, o);
        if (lane == 0)
            inv[r] = 1.0f / (sqrtf(acc) + EPS_);
    }
    __syncthreads();

    // ---- pass 2: aggregate + global L2 normalize ----
    float4 s = make_float4(0.f, 0.f, 0.f, 0.f);
    float local = 0.f;
    if (tid < 512) {
        #pragma unroll
        for (int r = 0; r < R_; r++) {
            const float4 v = vb4[r * 512 + tid];
            const float k = inv[r];
            s.x += v.x * k; s.y += v.y * k;
            s.z += v.z * k; s.w += v.w * k;
        }
        local = s.x * s.x + s.y * s.y + s.z * s.z + s.w * s.w;
    }

    #pragma unroll
    for (int o = 16; o > 0; o >>= 1)
        local += __shfl_xor_sync(0xffffffffu, local, o);
    __shared__ float ws[R_];
    if (lane == 0) ws[warp] = local;
    __syncthreads();
    __shared__ float s_invn;
    if (warp == 0) {
        float t = (lane < R_) ? ws[lane] : 0.f;
        #pragma unroll
        for (int o = 16; o > 0; o >>= 1)
            t += __shfl_xor_sync(0xffffffffu, t, o);
        if (lane == 0) s_invn = 1.0f / (sqrtf(t) + EPS_);
    }
    __syncthreads();

    if (tid < 512) {
        const float invn = s_invn;
        s.x *= invn; s.y *= invn; s.z *= invn; s.w *= invn;
        reinterpret_cast<float4*>(out)[(size_t)b * 512 + tid] = s;
    }
}

extern "C" void kernel_launch(void* const* d_in, const int* in_sizes, int n_in,
                              void* d_out, int out_size)
{
    const float* x = (const float*)d_in[0];
    float* out = (float*)d_out;

    float* vecs;
    cudaGetSymbolAddress((void**)&vecs, g_vecs);

    rpool_max_kernel<<<NPLANE, 64>>>(x, vecs);

    // PDL launch of the backend: it may be scheduled while the pool drains;
    // its griddepcontrol.wait provides the data dependency.
    cudaLaunchAttribute attrs[1];
    attrs[0].id = cudaLaunchAttributeProgrammaticStreamSerialization;
    attrs[0].val.programmaticStreamSerializationAllowed = 1;

    cudaLaunchConfig_t cfg = {};
    cfg.gridDim = dim3(B_, 1, 1);
    cfg.blockDim = dim3(672, 1, 1);
    cfg.dynamicSmemBytes = 0;
    cfg.stream = 0;
    cfg.attrs = attrs;
    cfg.numAttrs = 1;

    cudaLaunchKernelEx(&cfg, rpool_normagg_kernel,
                       (const float*)vecs, out);
}

// round 16
// speedup vs baseline: 1.0815x; 1.0004x over previous
#include <cuda_runtime.h>
#include <float.h>
#include <math.h>
#include <cstdint>

// x = [B=16, C=2048, H=48, W=64] fp32. 21 regions; 6 row ranges from 6 row
// segments (breakpoints 0,12,16,24,32,36,48).
#define B_  16
#define C_  2048
#define H_  48
#define W_  64
#define NPLANE (B_ * C_)
#define R_  21
#define EPS_ 1e-6f

#define CLU_  4                    // CTAs per batch (cluster size)
#define CH4_  (C_ / 4 / CLU_)      // float4 per chunk = 128

__device__ float g_vecs[B_ * R_ * C_];    // [b][r][c]

// RR0=[0,48) RR1=[0,32) RR2=[16,48) RR3=[0,24) RR4=[12,36) RR5=[24,48)
__constant__ int REG_RR[R_] = {
    0,
    0, 0,
    1, 1, 1,
    2, 2, 2,
    3, 3, 3, 3,
    4, 4, 4, 4,
    5, 5, 5, 5
};
__constant__ int REG_C0[R_] = {
    0,
    0, 16,
    0, 16, 32,
    0, 16, 32,
    0, 13, 26, 40,
    0, 13, 26, 40,
    0, 13, 26, 40
};
__constant__ int REG_C1[R_] = {
    64,
    48, 64,
    32, 48, 64,
    32, 48, 64,
    24, 37, 50, 64,
    24, 37, 50, 64,
    24, 37, 50, 64
};

__device__ __forceinline__ uint32_t smem_u32(const void* p) {
    return (uint32_t)__cvta_generic_to_shared(p);
}
__device__ __forceinline__ uint32_t mapa_rank(uint32_t addr, uint32_t rank) {
    uint32_t r;
    asm("mapa.shared::cluster.u32 %0, %1, %2;" : "=r"(r) : "r"(addr), "r"(rank));
    return r;
}
__device__ __forceinline__ float ld_dsmem(uint32_t addr) {
    float v;
    asm volatile("ld.shared::cluster.f32 %0, [%1];" : "=f"(v) : "r"(addr));
    return v;
}
#define CLUSTER_SYNC() do { \
    asm volatile("barrier.cluster.arrive.aligned;" ::: "memory"); \
    asm volatile("barrier.cluster.wait.aligned;" ::: "memory"); \
} while (0)

// ---------------------------------------------------------------------------
// Kernel 1 (R13-exact pool, proven ~69.4us, rel_err 1e-7): one block per
// (b,c) plane, 64 threads = one per column. Streaming (__ldcs) coalesced
// column-walk, 6 segment maxes in registers, 6 row-range maxes in smem, 21
// region reductions. launch_dependents AFTER the vecs stores (HW-guaranteed
// visibility to the dependent grid's griddepcontrol.wait).
// ---------------------------------------------------------------------------
__global__ __launch_bounds__(64) void rpool_max_kernel(
    const float* __restrict__ x, float* __restrict__ vecs)
{
    const int plane = blockIdx.x;             // b * C + c
    const float* __restrict__ p = x + (size_t)plane * (H_ * W_);
    const int col = threadIdx.x;              // 0..63

    float s0 = -FLT_MAX, s1 = -FLT_MAX, s2 = -FLT_MAX;
    float s3 = -FLT_MAX, s4 = -FLT_MAX, s5 = -FLT_MAX;

    #pragma unroll
    for (int r = 0; r < 12; r++)  s0 = fmaxf(s0, __ldcs(p + r * W_ + col));
    #pragma unroll
    for (int r = 12; r < 16; r++) s1 = fmaxf(s1, __ldcs(p + r * W_ + col));
    #pragma unroll
    for (int r = 16; r < 24; r++) s2 = fmaxf(s2, __ldcs(p + r * W_ + col));
    #pragma unroll
    for (int r = 24; r < 32; r++) s3 = fmaxf(s3, __ldcs(p + r * W_ + col));
    #pragma unroll
    for (int r = 32; r < 36; r++) s4 = fmaxf(s4, __ldcs(p + r * W_ + col));
    #pragma unroll
    for (int r = 36; r < 48; r++) s5 = fmaxf(s5, __ldcs(p + r * W_ + col));

    __shared__ float rr[6][W_];
    const float m012 = fmaxf(fmaxf(s0, s1), s2);
    const float m345 = fmaxf(fmaxf(s3, s4), s5);
    rr[0][col] = fmaxf(m012, m345);                     // rows [0,48)
    rr[1][col] = fmaxf(m012, s3);                       // rows [0,32)
    rr[2][col] = fmaxf(fmaxf(s2, s3), fmaxf(s4, s5));   // rows [16,48)
    rr[3][col] = m012;                                  // rows [0,24)
    rr[4][col] = fmaxf(fmaxf(s1, s2), fmaxf(s3, s4));   // rows [12,36)
    rr[5][col] = m345;                                  // rows [24,48)
    __syncthreads();

    const int warp = threadIdx.x >> 5;
    const int lane = threadIdx.x & 31;
    const int b = plane >> 11;          // / C_
    const int c = plane & (C_ - 1);     // % C_

    for (int reg = warp; reg < R_; reg += 2) {
        const int ri = REG_RR[reg];
        const int c0 = REG_C0[reg];
        const int c1 = REG_C1[reg];
        float m = -FLT_MAX;
        for (int cc = c0 + lane; cc < c1; cc += 32)
            m = fmaxf(m, rr[ri][cc]);
        #pragma unroll
        for (int o = 16; o > 0; o >>= 1)
            m = fmaxf(m, __shfl_xor_sync(0xffffffffu, m, o));
        if (lane == 0)
            vecs[((size_t)(b * R_ + reg)) * C_ + c] = m;
    }

    // All this CTA's vecs stores are above this point: safe to signal.
    asm volatile("griddepcontrol.launch_dependents;" ::: "memory");
}

// ---------------------------------------------------------------------------
// Kernel 2 (clustered backend): 64 CTAs (4-CTA cluster per batch) x 256
// threads. CTA `chunk` owns 512 channels of its batch.
// Pass 1: 8 warps compute 21 per-region PARTIAL sums of squares for the
//         chunk; DSMEM all-gather (4x21 floats) after cluster.sync -> inv[r].
// Pass 2: 128 threads aggregate the chunk's channels, DSMEM-exchange the
//         4 global-norm partials, scale, store. Deterministic; no atomics.
// ---------------------------------------------------------------------------
__global__ __launch_bounds__(256) __cluster_dims__(CLU_, 1, 1)
void rpool_normagg_kernel(const float* __restrict__ vecs,
                          float* __restrict__ out)
{
    const int bid = blockIdx.x;
    const int b = bid >> 2;                   // batch
    const int chunk = bid & 3;                // cluster rank
    const int tid = threadIdx.x;
    const int warp = tid >> 5, lane = tid & 31;

    __shared__ float my_part[R_];             // this chunk's 21 partials
    __shared__ float my_gn;                   // this chunk's global-norm part
    __shared__ float inv[R_];
    __shared__ float s_invn;
    __shared__ float wred[4];

    // Wait for the pool grid (PDL; HW-guaranteed memory visibility).
    asm volatile("griddepcontrol.wait;" ::: "memory");

    // chunk's view: region r, float4 i in [0,128)
    const float4* __restrict__ vb4 =
        reinterpret_cast<const float4*>(vecs + (size_t)b * R_ * C_)
        + chunk * CH4_;

    // ---- pass 1: partial sums of squares (warp w: regions w, w+8, w+16) ----
    for (int r = warp; r < R_; r += 8) {
        float acc = 0.f;
        #pragma unroll
        for (int k = 0; k < 4; k++) {
            const float4 v = vb4[r * 512 + lane + k * 32];
            acc += v.x * v.x + v.y * v.y + v.z * v.z + v.w * v.w;
        }
        #pragma unroll
        for (int o = 16; o > 0; o >>= 1)
            acc += __shfl_xor_sync(0xffffffffu, acc, o);
        if (lane == 0) my_part[r] = acc;
    }
    CLUSTER_SYNC();

    // all-gather partials from the 4 cluster CTAs
    if (tid < R_) {
        const uint32_t base = smem_u32(&my_part[tid]);
        float s = 0.f;
        #pragma unroll
        for (uint32_t rk = 0; rk < CLU_; rk++)
            s += ld_dsmem(mapa_rank(base, rk));
        inv[tid] = 1.0f / (sqrtf(s) + EPS_);
    }
    __syncthreads();

    // ---- pass 2: aggregate own chunk ----
    float4 s4 = make_float4(0.f, 0.f, 0.f, 0.f);
    float local = 0.f;
    if (tid < CH4_) {                         // 128 threads, 1 float4 each
        #pragma unroll
        for (int r = 0; r < R_; r++) {
            const float4 v = vb4[r * 512 + tid];
            const float k = inv[r];
            s4.x += v.x * k; s4.y += v.y * k;
            s4.z += v.z * k; s4.w += v.w * k;
        }
        local = s4.x * s4.x + s4.y * s4.y + s4.z * s4.z + s4.w * s4.w;
    }
    #pragma unroll
    for (int o = 16; o > 0; o >>= 1)
        local += __shfl_xor_sync(0xffffffffu, local, o);
    if (lane == 0 && warp < 4) wred[warp] = local;
    __syncthreads();
    if (tid == 0)
        my_gn = wred[0] + wred[1] + wred[2] + wred[3];
    CLUSTER_SYNC();

    if (tid == 0) {
        const uint32_t base = smem_u32(&my_gn);
        float t = 0.f;
        #pragma unroll
        for (uint32_t rk = 0; rk < CLU_; rk++)
            t += ld_dsmem(mapa_rank(base, rk));
        s_invn = 1.0f / (sqrtf(t) + EPS_);
    }
    __syncthreads();

    if (tid < CH4_) {
        const float invn = s_invn;
        s4.x *= invn; s4.y *= invn; s4.z *= invn; s4.w *= invn;
        reinterpret_cast<float4*>(out)[(size_t)b * 512 + chunk * CH4_ + tid] = s4;
    }
}

extern "C" void kernel_launch(void* const* d_in, const int* in_sizes, int n_in,
                              void* d_out, int out_size)
{
    const float* x = (const float*)d_in[0];
    float* out = (float*)d_out;

    float* vecs;
    cudaGetSymbolAddress((void**)&vecs, g_vecs);

    rpool_max_kernel<<<NPLANE, 64>>>(x, vecs);

    // PDL launch of the clustered backend (cluster dims are static on the
    // kernel via __cluster_dims__).
    cudaLaunchAttribute attrs[1];
    attrs[0].id = cudaLaunchAttributeProgrammaticStreamSerialization;
    attrs[0].val.programmaticStreamSerializationAllowed = 1;

    cudaLaunchConfig_t cfg = {};
    cfg.gridDim = dim3(B_ * CLU_, 1, 1);
    cfg.blockDim = dim3(256, 1, 1);
    cfg.dynamicSmemBytes = 0;
    cfg.stream = 0;
    cfg.attrs = attrs;
    cfg.numAttrs = 1;

    cudaLaunchKernelEx(&cfg, rpool_normagg_kernel,
                       (const float*)vecs, out);
}